// round 2
// baseline (speedup 1.0000x reference)
#include <cuda_runtime.h>
#include <cuda_bf16.h>
#include <cub/cub.cuh>
#include <math.h>

#define NNODES 10000
#define BATCH  2000
#define NPAIRS (BATCH*(BATCH-1)/2)   /* 1999000 */
#define EMAX   5000000

// ---------------- static device scratch (no allocations allowed) -----------
__device__ unsigned int       g_ekeys_a[EMAX];
__device__ unsigned int       g_ekeys_b[EMAX];
__device__ unsigned long long g_evals_a[EMAX];
__device__ unsigned long long g_evals_b[EMAX];
__device__ unsigned long long g_skeys_a[NNODES];
__device__ unsigned long long g_skeys_b[NNODES];
__device__ unsigned int       g_nodes_a[BATCH];
__device__ unsigned int       g_nodes_b[BATCH];
__device__ int                g_flags[NNODES];
__device__ unsigned char      g_temp[96u * 1024u * 1024u];

__device__ __forceinline__ unsigned int rotl32(unsigned int x, unsigned int d) {
    return (x << d) | (x >> (32u - d));
}

// ---------------- K1: partitionable-threefry gumbel scores -----------------
// JAX (jax_threefry_partitionable=True, the modern default):
//   per element w: 64-bit counter = w -> block (x0 = w>>32 = 0, x1 = w)
//   (o0, o1) = threefry2x32(key=[0,19], (x0, x1));  bits = o0 ^ o1
//   u = max(tiny, bitcast((bits>>9)|0x3f800000) - 1);  g = -log(-log(u))
//   score = (w>0 ? log(w) : -inf) + g
__global__ void k_scores() {
    int w = blockIdx.x * blockDim.x + threadIdx.x;
    if (w >= NNODES) return;

    const unsigned int k0 = 0u, k1 = 19u;
    const unsigned int ks[3] = { k0, k1, k0 ^ k1 ^ 0x1BD11BDAu };
    const unsigned int rotA[4] = {13u, 15u, 26u, 6u};
    const unsigned int rotB[4] = {17u, 29u, 16u, 24u};

    unsigned int x0 = 0u;                 // high 32 bits of 64-bit counter
    unsigned int x1 = (unsigned int)w;    // low 32 bits
    x0 += ks[0]; x1 += ks[1];
    #pragma unroll
    for (int i = 0; i < 5; i++) {
        #pragma unroll
        for (int r = 0; r < 4; r++) {
            unsigned int rot = (i & 1) ? rotB[r] : rotA[r];
            x0 += x1; x1 = rotl32(x1, rot); x1 ^= x0;
        }
        x0 += ks[(i + 1) % 3];
        x1 += ks[(i + 2) % 3] + (unsigned int)(i + 1);
    }
    unsigned int bits = x0 ^ x1;          // 32-bit fold of the two output lanes

    float f = __uint_as_float((bits >> 9) | 0x3F800000u) - 1.0f;
    float u = fmaxf(f, 1.17549435e-38f);
    float g = -logf(-logf(u));
    float s = (w > 0) ? (logf((float)w) + g) : -INFINITY;
    // monotone float->uint mapping for radix sort
    unsigned int b = __float_as_uint(s);
    unsigned int m = (b & 0x80000000u) ? ~b : (b | 0x80000000u);
    g_skeys_a[w] = ((unsigned long long)m << 32) | (unsigned int)w;
}

// ---------------- K2: take indices of the top-2000 keys --------------------
__global__ void k_extract() {
    int t = blockIdx.x * blockDim.x + threadIdx.x;
    if (t >= BATCH) return;
    g_nodes_a[t] = (unsigned int)(g_skeys_b[t] & 0xFFFFFFFFu);
}

// ---------------- K3: membership flags + batch_nodes output ----------------
__global__ void k_flags(float* out) {
    int t = blockIdx.x * blockDim.x + threadIdx.x;
    if (t >= NNODES) return;
    // binary search t in sorted g_nodes_b[0..BATCH)
    int lo = 0, hi = BATCH;
    unsigned int tv = (unsigned int)t;
    while (lo < hi) {
        int mid = (lo + hi) >> 1;
        if (g_nodes_b[mid] < tv) lo = mid + 1; else hi = mid;
    }
    g_flags[t] = (lo < BATCH && g_nodes_b[lo] == tv) ? 1 : 0;
    if (t < BATCH) out[t] = (float)g_nodes_b[t];
}

// ---------------- K4: batch_pairs -------------------------------------------
__global__ void k_pairs(float* out) {
    int p = blockIdx.x * blockDim.x + threadIdx.x;
    if (p >= NPAIRS) return;
    // invert: pairs before row i is g(i) = i*(2B-i-1)/2 ; find max i with g(i)<=p
    double a = 2.0 * BATCH - 1.0;
    double disc = a * a - 8.0 * (double)p;
    int i = (int)((a - sqrt(disc)) * 0.5);
    if (i < 0) i = 0;
    if (i > BATCH - 2) i = BATCH - 2;
    while (i > 0 && (long long)i * (2 * BATCH - i - 1) / 2 > (long long)p) i--;
    while ((long long)(i + 1) * (2 * BATCH - i - 2) / 2 <= (long long)p) i++;
    long long base = (long long)i * (2 * BATCH - i - 1) / 2;
    int j = i + 1 + (int)((long long)p - base);
    out[BATCH + p]          = (float)g_nodes_b[i];
    out[BATCH + NPAIRS + p] = (float)g_nodes_b[j];
}

// ---------------- K5: edge sort keys + packed payloads ----------------------
// key = flat_idx(i,j) (fits in 26 bits); value = time(32) | i(14) | j(14) | state(1)
__global__ void k_ekeys(const int* __restrict__ edges,
                        const float* __restrict__ times,
                        const int* __restrict__ states, int E) {
    int t = blockIdx.x * blockDim.x + threadIdx.x;
    if (t >= E) return;
    int i = edges[t];
    int j = edges[E + t];
    unsigned int flat = (unsigned int)(i * NNODES - (i * (i + 1)) / 2 + (j - i - 1));
    g_ekeys_a[t] = flat;
    unsigned int tb = __float_as_uint(times[t]);
    unsigned int st = (unsigned int)states[t] & 1u;
    g_evals_a[t] = ((unsigned long long)tb << 32) |
                   ((unsigned int)i << 18) | ((unsigned int)j << 4) | st;
}

// ---------------- K6: epilogue — write sorted edges, masked times/states ----
__global__ void k_out(float* __restrict__ out, int E) {
    int t = blockIdx.x * blockDim.x + threadIdx.x;
    if (t >= E) return;
    unsigned long long v = g_evals_b[t];
    int i  = (int)((v >> 18) & 0x3FFFu);
    int j  = (int)((v >> 4)  & 0x3FFFu);
    float tm = __uint_as_float((unsigned int)(v >> 32));
    int st = (int)(v & 1u);
    int m  = g_flags[i] & g_flags[j];

    long long OFF_E = (long long)BATCH + 2LL * NPAIRS;      // 4,000,000
    long long OFF_T = OFF_E + 2LL * E;                      // 14,000,000
    long long OFF_S = OFF_T + E;                            // 19,000,000
    long long OFF_M = OFF_S + E;                            // 24,000,000

    out[OFF_E + t]     = (float)i;
    out[OFF_E + E + t] = (float)j;
    out[OFF_T + t]     = m ? tm : 0.0f;
    out[OFF_S + t]     = m ? (float)st : 0.0f;
    out[OFF_M + t]     = (float)m;
}

// ---------------- launcher ---------------------------------------------------
extern "C" void kernel_launch(void* const* d_in, const int* in_sizes, int n_in,
                              void* d_out, int out_size) {
    const int*   edges  = (const int*)d_in[0];
    const float* times  = (const float*)d_in[1];
    const int*   states = (const int*)d_in[2];
    int E = in_sizes[1];
    if (E > EMAX) E = EMAX;
    float* out = (float*)d_out;

    // host pointers to device scratch (for cub)
    void *skeys_a, *skeys_b, *nodes_a, *nodes_b, *ekeys_a, *ekeys_b, *evals_a, *evals_b, *temp;
    cudaGetSymbolAddress(&skeys_a, g_skeys_a);
    cudaGetSymbolAddress(&skeys_b, g_skeys_b);
    cudaGetSymbolAddress(&nodes_a, g_nodes_a);
    cudaGetSymbolAddress(&nodes_b, g_nodes_b);
    cudaGetSymbolAddress(&ekeys_a, g_ekeys_a);
    cudaGetSymbolAddress(&ekeys_b, g_ekeys_b);
    cudaGetSymbolAddress(&evals_a, g_evals_a);
    cudaGetSymbolAddress(&evals_b, g_evals_b);
    cudaGetSymbolAddress(&temp,    g_temp);
    const size_t temp_cap = 96u * 1024u * 1024u;

    // 1) gumbel scores -> sortable 64-bit keys
    k_scores<<<(NNODES + 255) / 256, 256>>>();

    // 2) sort scores descending (only high 32 bits carry the score)
    size_t tb = 0;
    cub::DeviceRadixSort::SortKeysDescending(
        nullptr, tb, (const unsigned long long*)skeys_a,
        (unsigned long long*)skeys_b, NNODES, 32, 64);
    if (tb > temp_cap) tb = temp_cap;
    cub::DeviceRadixSort::SortKeysDescending(
        temp, tb, (const unsigned long long*)skeys_a,
        (unsigned long long*)skeys_b, NNODES, 32, 64);

    // 3) extract top-2000 node ids, sort ascending -> batch_nodes
    k_extract<<<(BATCH + 255) / 256, 256>>>();
    tb = 0;
    cub::DeviceRadixSort::SortKeys(
        nullptr, tb, (const unsigned int*)nodes_a,
        (unsigned int*)nodes_b, BATCH, 0, 16);
    if (tb > temp_cap) tb = temp_cap;
    cub::DeviceRadixSort::SortKeys(
        temp, tb, (const unsigned int*)nodes_a,
        (unsigned int*)nodes_b, BATCH, 0, 16);

    // 4) membership flags + batch_nodes output; batch_pairs output
    k_flags<<<(NNODES + 255) / 256, 256>>>(out);
    k_pairs<<<(NPAIRS + 255) / 256, 256>>>(out);

    // 5) edge keys/payloads, stable radix sort on 27-bit flat index
    k_ekeys<<<(E + 255) / 256, 256>>>(edges, times, states, E);
    tb = 0;
    cub::DeviceRadixSort::SortPairs(
        nullptr, tb, (const unsigned int*)ekeys_a, (unsigned int*)ekeys_b,
        (const unsigned long long*)evals_a, (unsigned long long*)evals_b,
        E, 0, 27);
    if (tb > temp_cap) tb = temp_cap;
    cub::DeviceRadixSort::SortPairs(
        temp, tb, (const unsigned int*)ekeys_a, (unsigned int*)ekeys_b,
        (const unsigned long long*)evals_a, (unsigned long long*)evals_b,
        E, 0, 27);

    // 6) epilogue
    k_out<<<(E + 255) / 256, 256>>>(out, E);
}

// round 3
// speedup vs baseline: 1.2534x; 1.2534x over previous
#include <cuda_runtime.h>
#include <cuda_bf16.h>
#include <cub/cub.cuh>
#include <math.h>

#define NNODES 10000
#define BATCH  2000
#define NPAIRS (BATCH*(BATCH-1)/2)   /* 1999000 */
#define EMAX   5000000
#define SEL_THREADS 1024

// ---------------- static device scratch (no allocations allowed) -----------
__device__ unsigned int g_ekeys_a[EMAX];
__device__ unsigned int g_ekeys_b[EMAX];
__device__ unsigned int g_evals_a[EMAX];
__device__ unsigned int g_evals_b[EMAX];
__device__ unsigned int g_scores[NNODES];
__device__ unsigned int g_nodes[BATCH];
__device__ int          g_flags[NNODES];
__device__ unsigned char g_temp[96u * 1024u * 1024u];

__device__ __forceinline__ unsigned int rotl32(unsigned int x, unsigned int d) {
    return (x << d) | (x >> (32u - d));
}

// ---------------- K1: partitionable-threefry gumbel scores -----------------
// per element w: block (x0=0, x1=w), key=[0,19]; bits = o0 ^ o1
// u = max(tiny, bitcast((bits>>9)|0x3f800000)-1); g = -log(-log(u))
// score = (w>0 ? log(w) : -inf) + g ; stored as monotone-mapped u32
__global__ void k_scores() {
    int w = blockIdx.x * blockDim.x + threadIdx.x;
    if (w >= NNODES) return;

    const unsigned int k0 = 0u, k1 = 19u;
    const unsigned int ks[3] = { k0, k1, k0 ^ k1 ^ 0x1BD11BDAu };
    const unsigned int rotA[4] = {13u, 15u, 26u, 6u};
    const unsigned int rotB[4] = {17u, 29u, 16u, 24u};

    unsigned int x0 = 0u;
    unsigned int x1 = (unsigned int)w;
    x0 += ks[0]; x1 += ks[1];
    #pragma unroll
    for (int i = 0; i < 5; i++) {
        #pragma unroll
        for (int r = 0; r < 4; r++) {
            unsigned int rot = (i & 1) ? rotB[r] : rotA[r];
            x0 += x1; x1 = rotl32(x1, rot); x1 ^= x0;
        }
        x0 += ks[(i + 1) % 3];
        x1 += ks[(i + 2) % 3] + (unsigned int)(i + 1);
    }
    unsigned int bits = x0 ^ x1;

    float f = __uint_as_float((bits >> 9) | 0x3F800000u) - 1.0f;
    float u = fmaxf(f, 1.17549435e-38f);
    float g = -logf(-logf(u));
    float s = (w > 0) ? (logf((float)w) + g) : -INFINITY;
    unsigned int b = __float_as_uint(s);
    unsigned int m = (b & 0x80000000u) ? ~b : (b | 0x80000000u);
    g_scores[w] = m;
}

// ---------------- K2: single-block exact top-2000 radix select -------------
// Finds the 2000th-largest mapped score (jax top_k tie-break: lowest index
// wins among equals), sets g_flags, emits sorted batch_nodes + out[0..2000).
__global__ void __launch_bounds__(SEL_THREADS) k_select(float* __restrict__ out) {
    __shared__ unsigned int s[NNODES];          // 40 KB
    __shared__ unsigned int hist[256];
    __shared__ unsigned int sh_b, sh_rem;
    __shared__ unsigned int sh_run_eq, sh_run_sel;
    typedef cub::BlockScan<unsigned int, SEL_THREADS> Scan;
    __shared__ typename Scan::TempStorage scan_tmp;

    int tid = threadIdx.x;
    for (int e = tid; e < NNODES; e += SEL_THREADS) s[e] = g_scores[e];
    if (tid == 0) { sh_rem = BATCH; sh_run_eq = 0; sh_run_sel = 0; }
    __syncthreads();

    unsigned int prefix = 0;
    #pragma unroll
    for (int shift = 24; shift >= 0; shift -= 8) {
        if (tid < 256) hist[tid] = 0;
        __syncthreads();
        unsigned int mask_hi = (shift == 24) ? 0u : (0xFFFFFFFFu << (shift + 8));
        for (int e = tid; e < NNODES; e += SEL_THREADS) {
            unsigned int v = s[e];
            if (((v ^ prefix) & mask_hi) == 0u)
                atomicAdd(&hist[(v >> shift) & 255u], 1u);
        }
        __syncthreads();
        if (tid == 0) {
            unsigned int rem = sh_rem, acc = 0; int b = 0;
            for (int k = 255; k >= 0; k--) {
                unsigned int c = hist[k];
                if (acc + c >= rem) { b = k; break; }
                acc += c;
            }
            sh_b = (unsigned int)b;
            sh_rem = rem - acc;     // remaining to take from bucket b
        }
        __syncthreads();
        prefix |= sh_b << shift;
        __syncthreads();
    }
    unsigned int thr = prefix;
    unsigned int rem = sh_rem;      // # of ==thr to take (lowest indices first)

    // ordered sweep: flags + compacted ascending node list
    for (int base = 0; base < NNODES; base += SEL_THREADS) {
        int e = base + tid;
        unsigned int v = (e < NNODES) ? s[e] : 0u;
        unsigned int is_eq = (e < NNODES && v == thr) ? 1u : 0u;
        unsigned int is_gt = (e < NNODES && v >  thr) ? 1u : 0u;
        unsigned int eq_rank, eq_tot;
        Scan(scan_tmp).ExclusiveSum(is_eq, eq_rank, eq_tot);
        __syncthreads();
        unsigned int sel = is_gt | ((is_eq && (sh_run_eq + eq_rank) < rem) ? 1u : 0u);
        unsigned int pos, sel_tot;
        Scan(scan_tmp).ExclusiveSum(sel, pos, sel_tot);
        __syncthreads();
        unsigned int gpos = sh_run_sel + pos;
        if (e < NNODES) {
            g_flags[e] = (int)sel;
            if (sel) { g_nodes[gpos] = (unsigned int)e; out[gpos] = (float)e; }
        }
        __syncthreads();
        if (tid == 0) { sh_run_eq += eq_tot; sh_run_sel += sel_tot; }
        __syncthreads();
    }
}

// ---------------- K3: batch_pairs -------------------------------------------
__global__ void k_pairs(float* __restrict__ out) {
    int p = blockIdx.x * blockDim.x + threadIdx.x;
    if (p >= NPAIRS) return;
    const float A = 2.0f * BATCH - 1.0f;
    float disc = A * A - 8.0f * (float)p;
    int i = (int)((A - sqrtf(fmaxf(disc, 0.0f))) * 0.5f);
    if (i < 0) i = 0;
    if (i > BATCH - 2) i = BATCH - 2;
    while (i > 0 && (long long)i * (2 * BATCH - i - 1) / 2 > (long long)p) i--;
    while ((long long)(i + 1) * (2 * BATCH - i - 2) / 2 <= (long long)p) i++;
    long long bse = (long long)i * (2 * BATCH - i - 1) / 2;
    int j = i + 1 + (int)((long long)p - bse);
    out[BATCH + p]          = (float)__ldg(&g_nodes[i]);
    out[BATCH + NPAIRS + p] = (float)__ldg(&g_nodes[j]);
}

// ---------------- K4: edge keys + values ------------------------------------
// key = flat(26b)<<6 | state(1b)  (sorted on bits [6,32) -> stable on flat)
// val = time bits
__global__ void k_ekeys(const int* __restrict__ edges,
                        const float* __restrict__ times,
                        const int* __restrict__ states, int E) {
    int t = blockIdx.x * blockDim.x + threadIdx.x;
    if (t >= E) return;
    int i = edges[t];
    int j = edges[E + t];
    unsigned int flat = (unsigned int)(i * NNODES - (i * (i + 1)) / 2 + (j - i - 1));
    g_ekeys_a[t] = (flat << 6) | ((unsigned int)states[t] & 1u);
    g_evals_a[t] = __float_as_uint(times[t]);
}

// ---------------- K5: epilogue — decode flat -> (i,j), write outputs --------
__device__ __forceinline__ long long rowbase(int i) {
    return (long long)i * (2 * NNODES - 1 - i) / 2;
}
__global__ void k_out(float* __restrict__ out, int E) {
    int t = blockIdx.x * blockDim.x + threadIdx.x;
    if (t >= E) return;
    unsigned int key = g_ekeys_b[t];
    unsigned int flat = key >> 6;
    int st = (int)(key & 1u);
    float tm = __uint_as_float(g_evals_b[t]);

    // invert flat -> i (float approx + exact integer fixup)
    const float A = 2.0f * NNODES - 1.0f;
    float disc = A * A - 8.0f * (float)flat;
    int i = (int)((A - sqrtf(fmaxf(disc, 0.0f))) * 0.5f);
    if (i < 0) i = 0;
    if (i > NNODES - 2) i = NNODES - 2;
    while (i > 0 && rowbase(i) > (long long)flat) i--;
    while (rowbase(i + 1) <= (long long)flat) i++;
    int j = (int)((long long)flat - rowbase(i)) + i + 1;

    int m = g_flags[i] & g_flags[j];

    const long long OFF_E = (long long)BATCH + 2LL * NPAIRS;  // 4,000,000
    const long long OFF_T = OFF_E + 2LL * E;                  // 14,000,000
    const long long OFF_S = OFF_T + E;                        // 19,000,000
    const long long OFF_M = OFF_S + E;                        // 24,000,000

    out[OFF_E + t]     = (float)i;
    out[OFF_E + E + t] = (float)j;
    out[OFF_T + t]     = m ? tm : 0.0f;
    out[OFF_S + t]     = m ? (float)st : 0.0f;
    out[OFF_M + t]     = (float)m;
}

// ---------------- launcher ---------------------------------------------------
extern "C" void kernel_launch(void* const* d_in, const int* in_sizes, int n_in,
                              void* d_out, int out_size) {
    const int*   edges  = (const int*)d_in[0];
    const float* times  = (const float*)d_in[1];
    const int*   states = (const int*)d_in[2];
    int E = in_sizes[1];
    if (E > EMAX) E = EMAX;
    float* out = (float*)d_out;

    void *ekeys_a, *ekeys_b, *evals_a, *evals_b, *temp;
    cudaGetSymbolAddress(&ekeys_a, g_ekeys_a);
    cudaGetSymbolAddress(&ekeys_b, g_ekeys_b);
    cudaGetSymbolAddress(&evals_a, g_evals_a);
    cudaGetSymbolAddress(&evals_b, g_evals_b);
    cudaGetSymbolAddress(&temp,    g_temp);
    const size_t temp_cap = 96u * 1024u * 1024u;

    // edge keys first so the big sort starts ASAP
    k_ekeys<<<(E + 255) / 256, 256>>>(edges, times, states, E);

    // node chain: scores -> single-block exact top-k select
    k_scores<<<(NNODES + 255) / 256, 256>>>();
    k_select<<<1, SEL_THREADS>>>(out);
    k_pairs<<<(NPAIRS + 255) / 256, 256>>>(out);

    // stable radix sort of 5M edges on bits [6,32) of the packed key
    size_t tb = 0;
    cub::DeviceRadixSort::SortPairs(
        nullptr, tb, (const unsigned int*)ekeys_a, (unsigned int*)ekeys_b,
        (const unsigned int*)evals_a, (unsigned int*)evals_b, E, 6, 32);
    if (tb > temp_cap) tb = temp_cap;
    cub::DeviceRadixSort::SortPairs(
        temp, tb, (const unsigned int*)ekeys_a, (unsigned int*)ekeys_b,
        (const unsigned int*)evals_a, (unsigned int*)evals_b, E, 6, 32);

    // epilogue
    k_out<<<(E + 255) / 256, 256>>>(out, E);
}

// round 4
// speedup vs baseline: 1.4345x; 1.1445x over previous
#include <cuda_runtime.h>
#include <cuda_bf16.h>
#include <cub/cub.cuh>
#include <math.h>

#define NNODES 10000
#define BATCH  2000
#define NPAIRS (BATCH*(BATCH-1)/2)   /* 1999000 */
#define EMAX   5000000
#define SEL_THREADS 1024

// ---------------- static device scratch (no allocations allowed) -----------
__device__ unsigned int g_ekeys_a[EMAX];
__device__ unsigned int g_ekeys_b[EMAX];
__device__ unsigned int g_evals_a[EMAX];
__device__ unsigned int g_evals_b[EMAX];
__device__ unsigned int g_scores[NNODES];
__device__ unsigned int g_nodes[BATCH];
__device__ int          g_flags[NNODES];
__device__ unsigned char g_temp[96u * 1024u * 1024u];

__device__ __forceinline__ unsigned int rotl32(unsigned int x, unsigned int d) {
    return (x << d) | (x >> (32u - d));
}

// ---------------- K1: partitionable-threefry gumbel scores -----------------
__global__ void k_scores() {
    int w = blockIdx.x * blockDim.x + threadIdx.x;
    if (w >= NNODES) return;

    const unsigned int k0 = 0u, k1 = 19u;
    const unsigned int ks[3] = { k0, k1, k0 ^ k1 ^ 0x1BD11BDAu };
    const unsigned int rotA[4] = {13u, 15u, 26u, 6u};
    const unsigned int rotB[4] = {17u, 29u, 16u, 24u};

    unsigned int x0 = 0u;
    unsigned int x1 = (unsigned int)w;
    x0 += ks[0]; x1 += ks[1];
    #pragma unroll
    for (int i = 0; i < 5; i++) {
        #pragma unroll
        for (int r = 0; r < 4; r++) {
            unsigned int rot = (i & 1) ? rotB[r] : rotA[r];
            x0 += x1; x1 = rotl32(x1, rot); x1 ^= x0;
        }
        x0 += ks[(i + 1) % 3];
        x1 += ks[(i + 2) % 3] + (unsigned int)(i + 1);
    }
    unsigned int bits = x0 ^ x1;

    float f = __uint_as_float((bits >> 9) | 0x3F800000u) - 1.0f;
    float u = fmaxf(f, 1.17549435e-38f);
    float g = -logf(-logf(u));
    float s = (w > 0) ? (logf((float)w) + g) : -INFINITY;
    unsigned int b = __float_as_uint(s);
    unsigned int m = (b & 0x80000000u) ? ~b : (b | 0x80000000u);
    g_scores[w] = m;
}

// ---------------- K2: single-block exact top-2000 radix select -------------
__global__ void __launch_bounds__(SEL_THREADS) k_select(float* __restrict__ out) {
    __shared__ unsigned int s[NNODES];          // 40 KB
    __shared__ unsigned int hist[256];
    __shared__ unsigned int sh_b, sh_rem;
    __shared__ unsigned int sh_run_eq, sh_run_sel;
    typedef cub::BlockScan<unsigned int, SEL_THREADS> Scan;
    __shared__ typename Scan::TempStorage scan_tmp;

    int tid = threadIdx.x;
    for (int e = tid; e < NNODES; e += SEL_THREADS) s[e] = g_scores[e];
    if (tid == 0) { sh_rem = BATCH; sh_run_eq = 0; sh_run_sel = 0; }
    __syncthreads();

    unsigned int prefix = 0;
    #pragma unroll
    for (int shift = 24; shift >= 0; shift -= 8) {
        if (tid < 256) hist[tid] = 0;
        __syncthreads();
        unsigned int mask_hi = (shift == 24) ? 0u : (0xFFFFFFFFu << (shift + 8));
        for (int e = tid; e < NNODES; e += SEL_THREADS) {
            unsigned int v = s[e];
            if (((v ^ prefix) & mask_hi) == 0u)
                atomicAdd(&hist[(v >> shift) & 255u], 1u);
        }
        __syncthreads();
        if (tid == 0) {
            unsigned int rem = sh_rem, acc = 0; int b = 0;
            for (int k = 255; k >= 0; k--) {
                unsigned int c = hist[k];
                if (acc + c >= rem) { b = k; break; }
                acc += c;
            }
            sh_b = (unsigned int)b;
            sh_rem = rem - acc;
        }
        __syncthreads();
        prefix |= sh_b << shift;
        __syncthreads();
    }
    unsigned int thr = prefix;
    unsigned int rem = sh_rem;

    for (int base = 0; base < NNODES; base += SEL_THREADS) {
        int e = base + tid;
        unsigned int v = (e < NNODES) ? s[e] : 0u;
        unsigned int is_eq = (e < NNODES && v == thr) ? 1u : 0u;
        unsigned int is_gt = (e < NNODES && v >  thr) ? 1u : 0u;
        unsigned int eq_rank, eq_tot;
        Scan(scan_tmp).ExclusiveSum(is_eq, eq_rank, eq_tot);
        __syncthreads();
        unsigned int sel = is_gt | ((is_eq && (sh_run_eq + eq_rank) < rem) ? 1u : 0u);
        unsigned int pos, sel_tot;
        Scan(scan_tmp).ExclusiveSum(sel, pos, sel_tot);
        __syncthreads();
        unsigned int gpos = sh_run_sel + pos;
        if (e < NNODES) {
            g_flags[e] = (int)sel;
            if (sel) { g_nodes[gpos] = (unsigned int)e; out[gpos] = (float)e; }
        }
        __syncthreads();
        if (tid == 0) { sh_run_eq += eq_tot; sh_run_sel += sel_tot; }
        __syncthreads();
    }
}

// ---------------- K3: batch_pairs -------------------------------------------
__global__ void k_pairs(float* __restrict__ out) {
    int p = blockIdx.x * blockDim.x + threadIdx.x;
    if (p >= NPAIRS) return;
    const float A = 2.0f * BATCH - 1.0f;
    float disc = A * A - 8.0f * (float)p;
    int i = (int)((A - sqrtf(fmaxf(disc, 0.0f))) * 0.5f);
    if (i < 0) i = 0;
    if (i > BATCH - 2) i = BATCH - 2;
    while (i > 0 && (long long)i * (2 * BATCH - i - 1) / 2 > (long long)p) i--;
    while ((long long)(i + 1) * (2 * BATCH - i - 2) / 2 <= (long long)p) i++;
    long long bse = (long long)i * (2 * BATCH - i - 1) / 2;
    int j = i + 1 + (int)((long long)p - bse);
    out[BATCH + p]          = (float)__ldg(&g_nodes[i]);
    out[BATCH + NPAIRS + p] = (float)__ldg(&g_nodes[j]);
}

// ---------------- K4: edge keys + values (vectorized, 4 edges/thread) -------
// key = flat(26b)<<6 | state(1b); val = time bits
__global__ void k_ekeys4(const int* __restrict__ edges,
                         const float* __restrict__ times,
                         const int* __restrict__ states, int E) {
    int t4 = (blockIdx.x * blockDim.x + threadIdx.x) * 4;
    if (t4 + 3 >= E) {   // scalar tail
        for (int t = t4; t < E; t++) {
            int i = edges[t], j = edges[E + t];
            unsigned int flat = (unsigned int)(i * NNODES - (i * (i + 1)) / 2 + (j - i - 1));
            g_ekeys_a[t] = (flat << 6) | ((unsigned int)states[t] & 1u);
            g_evals_a[t] = __float_as_uint(times[t]);
        }
        return;
    }
    int4 iv = *(const int4*)(edges + t4);
    int4 jv = *(const int4*)(edges + E + t4);
    int4 sv = *(const int4*)(states + t4);
    uint4 tv = *(const uint4*)((const unsigned int*)times + t4);

    uint4 kv;
    kv.x = ((unsigned int)(iv.x * NNODES - (iv.x * (iv.x + 1)) / 2 + (jv.x - iv.x - 1)) << 6) | ((unsigned int)sv.x & 1u);
    kv.y = ((unsigned int)(iv.y * NNODES - (iv.y * (iv.y + 1)) / 2 + (jv.y - iv.y - 1)) << 6) | ((unsigned int)sv.y & 1u);
    kv.z = ((unsigned int)(iv.z * NNODES - (iv.z * (iv.z + 1)) / 2 + (jv.z - iv.z - 1)) << 6) | ((unsigned int)sv.z & 1u);
    kv.w = ((unsigned int)(iv.w * NNODES - (iv.w * (iv.w + 1)) / 2 + (jv.w - iv.w - 1)) << 6) | ((unsigned int)sv.w & 1u);

    *(uint4*)(g_ekeys_a + t4) = kv;
    *(uint4*)(g_evals_a + t4) = tv;
}

// ---------------- K5: epilogue (vectorized, 4 edges/thread) ------------------
__device__ __forceinline__ long long rowbase(int i) {
    return (long long)i * (2 * NNODES - 1 - i) / 2;
}
__device__ __forceinline__ void decode_flat(unsigned int flat, int& i, int& j) {
    const float A = 2.0f * NNODES - 1.0f;
    float disc = A * A - 8.0f * (float)flat;
    i = (int)((A - sqrtf(fmaxf(disc, 0.0f))) * 0.5f);
    if (i < 0) i = 0;
    if (i > NNODES - 2) i = NNODES - 2;
    while (i > 0 && rowbase(i) > (long long)flat) i--;
    while (rowbase(i + 1) <= (long long)flat) i++;
    j = (int)((long long)flat - rowbase(i)) + i + 1;
}

__global__ void k_out4(float* __restrict__ out, int E) {
    int t4 = (blockIdx.x * blockDim.x + threadIdx.x) * 4;
    const long long OFF_E = (long long)BATCH + 2LL * NPAIRS;  // 4,000,000
    const long long OFF_T = OFF_E + 2LL * E;                  // 14,000,000
    const long long OFF_S = OFF_T + E;                        // 19,000,000
    const long long OFF_M = OFF_S + E;                        // 24,000,000

    if (t4 + 3 >= E) {   // scalar tail
        for (int t = t4; t < E; t++) {
            unsigned int key = g_ekeys_b[t];
            int i, j; decode_flat(key >> 6, i, j);
            int st = (int)(key & 1u);
            float tm = __uint_as_float(g_evals_b[t]);
            int m = g_flags[i] & g_flags[j];
            out[OFF_E + t]     = (float)i;
            out[OFF_E + E + t] = (float)j;
            out[OFF_T + t]     = m ? tm : 0.0f;
            out[OFF_S + t]     = m ? (float)st : 0.0f;
            out[OFF_M + t]     = (float)m;
        }
        return;
    }

    uint4 kv = *(const uint4*)(g_ekeys_b + t4);
    uint4 vv = *(const uint4*)(g_evals_b + t4);

    int i0, j0, i1, j1, i2, j2, i3, j3;
    decode_flat(kv.x >> 6, i0, j0);
    decode_flat(kv.y >> 6, i1, j1);
    decode_flat(kv.z >> 6, i2, j2);
    decode_flat(kv.w >> 6, i3, j3);

    int m0 = g_flags[i0] & g_flags[j0];
    int m1 = g_flags[i1] & g_flags[j1];
    int m2 = g_flags[i2] & g_flags[j2];
    int m3 = g_flags[i3] & g_flags[j3];

    *(float4*)(out + OFF_E + t4)     = make_float4((float)i0, (float)i1, (float)i2, (float)i3);
    *(float4*)(out + OFF_E + E + t4) = make_float4((float)j0, (float)j1, (float)j2, (float)j3);
    *(float4*)(out + OFF_T + t4) = make_float4(
        m0 ? __uint_as_float(vv.x) : 0.0f, m1 ? __uint_as_float(vv.y) : 0.0f,
        m2 ? __uint_as_float(vv.z) : 0.0f, m3 ? __uint_as_float(vv.w) : 0.0f);
    *(float4*)(out + OFF_S + t4) = make_float4(
        m0 ? (float)(kv.x & 1u) : 0.0f, m1 ? (float)(kv.y & 1u) : 0.0f,
        m2 ? (float)(kv.z & 1u) : 0.0f, m3 ? (float)(kv.w & 1u) : 0.0f);
    *(float4*)(out + OFF_M + t4) = make_float4((float)m0, (float)m1, (float)m2, (float)m3);
}

// ---------------- launcher ---------------------------------------------------
extern "C" void kernel_launch(void* const* d_in, const int* in_sizes, int n_in,
                              void* d_out, int out_size) {
    const int*   edges  = (const int*)d_in[0];
    const float* times  = (const float*)d_in[1];
    const int*   states = (const int*)d_in[2];
    int E = in_sizes[1];
    if (E > EMAX) E = EMAX;
    float* out = (float*)d_out;

    static cudaStream_t s_side = nullptr;
    static cudaEvent_t ev_fork = nullptr, ev_join = nullptr;
    if (s_side == nullptr) {
        cudaStreamCreateWithFlags(&s_side, cudaStreamNonBlocking);
        cudaEventCreateWithFlags(&ev_fork, cudaEventDisableTiming);
        cudaEventCreateWithFlags(&ev_join, cudaEventDisableTiming);
    }

    void *ekeys_a, *ekeys_b, *evals_a, *evals_b, *temp;
    cudaGetSymbolAddress(&ekeys_a, g_ekeys_a);
    cudaGetSymbolAddress(&ekeys_b, g_ekeys_b);
    cudaGetSymbolAddress(&evals_a, g_evals_a);
    cudaGetSymbolAddress(&evals_b, g_evals_b);
    cudaGetSymbolAddress(&temp,    g_temp);
    const size_t temp_cap = 96u * 1024u * 1024u;

    // ---- fork: node chain on side stream, overlapping the edge sort --------
    cudaEventRecord(ev_fork, 0);
    cudaStreamWaitEvent(s_side, ev_fork, 0);
    k_scores<<<(NNODES + 255) / 256, 256, 0, s_side>>>();
    k_select<<<1, SEL_THREADS, 0, s_side>>>(out);
    k_pairs<<<(NPAIRS + 255) / 256, 256, 0, s_side>>>(out);
    cudaEventRecord(ev_join, s_side);

    // ---- main: edge keygen + stable radix sort on bits [6,32) --------------
    k_ekeys4<<<(E / 4 + 255) / 256, 256>>>(edges, times, states, E);

    size_t tb = 0;
    cub::DeviceRadixSort::SortPairs(
        nullptr, tb, (const unsigned int*)ekeys_a, (unsigned int*)ekeys_b,
        (const unsigned int*)evals_a, (unsigned int*)evals_b, E, 6, 32);
    if (tb > temp_cap) tb = temp_cap;
    cub::DeviceRadixSort::SortPairs(
        temp, tb, (const unsigned int*)ekeys_a, (unsigned int*)ekeys_b,
        (const unsigned int*)evals_a, (unsigned int*)evals_b, E, 6, 32);

    // ---- join + epilogue ----------------------------------------------------
    cudaStreamWaitEvent(0, ev_join, 0);
    k_out4<<<(E / 4 + 255) / 256, 256>>>(out, E);
}